// round 13
// baseline (speedup 1.0000x reference)
#include <cuda_runtime.h>
#include <cuda_bf16.h>
#include <cuda_fp16.h>
#include <math.h>
#include <cstdint>

#define NN 100000
#define DD 128
#define EMAXM 1600000
#define EMAXT 1800000
#define NBMAX 512

// ---- static scratch (no allocation allowed) ----
__device__ float  g_agg[NN * DD];
__device__ float  g_norm[NN];
__device__ float  g_ns[NN];               // norm * quant-scale
__device__ float  g_scale[NN];            // quant-scale (feats only)
__device__ int    g_deg[NN];
__device__ int    g_indeg[NN];
__device__ float4 g_efsum[NN];
__device__ int    g_off[NN];
__device__ int    g_cursor[NN];
__device__ int    g_bsum[NBMAX];
__device__ int    g_boff[NBMAX];
__device__ float  g_att[EMAXM];
__device__ int2   g_edge[EMAXT];          // CSR: {src, coef} grouped by dst
__device__ __align__(16) uint32_t g_h8[NN * 32];   // int8 rows, 4 vals per word
__device__ __align__(16) uint8_t g_Bt[4 * 32768];  // prepacked B tiles

__device__ __forceinline__ void red_add_v4(float* p, float x, float y, float z, float w) {
    asm volatile("red.global.add.v4.f32 [%0], {%1,%2,%3,%4};"
                 :: "l"(p), "f"(x), "f"(y), "f"(z), "f"(w) : "memory");
}
__device__ __forceinline__ uint32_t smem_u32(const void* p) {
    uint32_t a;
    asm("{ .reg .u64 t; cvta.to.shared.u64 t, %1; cvt.u32.u64 %0, t; }" : "=r"(a) : "l"(p));
    return a;
}
// swizzled byte offset inside a 128-row x 64-col bf16 tile (128B rows)
__device__ __forceinline__ uint32_t swz(int row, int col) {
    return (uint32_t)(row * 128 + ((((col >> 3) ^ (row & 7)) << 4)) + ((col & 7) << 1));
}

// ======================= graph-prep kernels =================================
__global__ void k_init(int n) {
    int stride = gridDim.x * blockDim.x;
    for (int i = blockIdx.x * blockDim.x + threadIdx.x; i < n; i += stride) {
        g_deg[i] = 0;
        g_indeg[i] = 0;
        g_efsum[i] = make_float4(0.f, 0.f, 0.f, 0.f);
    }
}

// int8 quantization of feats: warp per node, per-row scale
__global__ void k_h8(const float4* __restrict__ feats, int n) {
    int gtid = blockIdx.x * blockDim.x + threadIdx.x;
    int v = gtid >> 5;
    int lane = gtid & 31;
    if (v >= n) return;
    float4 f = feats[v * 32 + lane];
    float m = fmaxf(fmaxf(fabsf(f.x), fabsf(f.y)), fmaxf(fabsf(f.z), fabsf(f.w)));
#pragma unroll
    for (int o = 16; o > 0; o >>= 1)
        m = fmaxf(m, __shfl_xor_sync(0xffffffffu, m, o));
    float inv = (m > 0.f) ? 127.f / m : 0.f;
    int b0 = __float2int_rn(f.x * inv);
    int b1 = __float2int_rn(f.y * inv);
    int b2 = __float2int_rn(f.z * inv);
    int b3 = __float2int_rn(f.w * inv);
    uint32_t w = (uint32_t)(b0 & 0xff) | ((uint32_t)(b1 & 0xff) << 8) |
                 ((uint32_t)(b2 & 0xff) << 16) | ((uint32_t)(b3 & 0xff) << 24);
    g_h8[v * 32 + lane] = w;
    if (lane == 0) g_scale[v] = m * (1.f / 127.f);
}

__global__ void k_prepB(const float* __restrict__ Wmsg, const float* __restrict__ Wskip) {
    int w = blockIdx.x * blockDim.x + threadIdx.x;
    if (w >= 16384) return;
    int phase = w >> 13;
    int j = (w >> 6) & 127;
    int kp = w & 63;
    int k = kp * 2;
    const float* W = phase ? Wskip : Wmsg;
    float v0 = W[j * DD + k], v1 = W[j * DD + k + 1];
    __nv_bfloat16 h0 = __float2bfloat16(v0), h1 = __float2bfloat16(v1);
    float l0 = v0 - __bfloat162float(h0), l1 = v1 - __bfloat162float(h1);
    __nv_bfloat16 q0 = __float2bfloat16(l0), q1 = __float2bfloat16(l1);
    uint32_t hw = (uint32_t)__bfloat16_as_ushort(h0) | ((uint32_t)__bfloat16_as_ushort(h1) << 16);
    uint32_t lw = (uint32_t)__bfloat16_as_ushort(q0) | ((uint32_t)__bfloat16_as_ushort(q1) << 16);
    int kc2 = k >> 6;
    int kin = k & 63;
    int tile = phase * 2 + kc2;
    uint32_t off = swz(j, kin);
    *(uint32_t*)(g_Bt + tile * 32768 + off) = hw;
    *(uint32_t*)(g_Bt + tile * 32768 + 16384 + off) = lw;
}

__global__ void k_count(const int* __restrict__ srcE, const int* __restrict__ dstE,
                        const float4* __restrict__ ef, const int* __restrict__ dstA,
                        const float* __restrict__ W_att, const float* __restrict__ b_att,
                        int eM, int eA) {
    int stride = gridDim.x * blockDim.x;
    int i0 = blockIdx.x * blockDim.x + threadIdx.x;
    float w0 = W_att[0], w1 = W_att[1], w2 = W_att[2], w3 = W_att[3], bb = b_att[0];
    for (int e = i0; e < eM; e += stride) {
        atomicAdd(&g_deg[srcE[e]], 1);
        int d = dstE[e];
        atomicAdd(&g_indeg[d], 1);
        float4 f = ef[e];
        red_add_v4((float*)&g_efsum[d], f.x, f.y, f.z, f.w);
        float x = w0 * f.x + w1 * f.y + w2 * f.z + w3 * f.w + bb;
        g_att[e] = 1.f / (1.f + __expf(-x));
    }
    for (int e = i0; e < eA; e += stride)
        atomicAdd(&g_indeg[dstA[e]], 1);
}

__global__ void k_scan1(int n) {
    int t = blockIdx.x * 256 + threadIdx.x;
    int v = (t < n) ? g_indeg[t] : 0;
    if (t < n) {
        int dg = g_deg[t];
        float nr = (dg > 0) ? rsqrtf((float)dg) : 0.f;
        g_norm[t] = nr;
        g_ns[t] = nr * g_scale[t];
    }
    __shared__ int sh[256];
    sh[threadIdx.x] = v;
    __syncthreads();
    for (int o = 128; o > 0; o >>= 1) {
        if (threadIdx.x < o) sh[threadIdx.x] += sh[threadIdx.x + o];
        __syncthreads();
    }
    if (threadIdx.x == 0) g_bsum[blockIdx.x] = sh[0];
}

__global__ void k_scan2(int nb) {
    __shared__ int sh[NBMAX];
    int t = threadIdx.x;
    int v = (t < nb) ? g_bsum[t] : 0;
    sh[t] = v;
    __syncthreads();
    for (int o = 1; o < NBMAX; o <<= 1) {
        int x = (t >= o) ? sh[t - o] : 0;
        __syncthreads();
        sh[t] += x;
        __syncthreads();
    }
    if (t < nb) g_boff[t] = sh[t] - v;
}

__global__ void k_scan3(int n) {
    __shared__ int sh[256];
    int t = blockIdx.x * 256 + threadIdx.x;
    int v = (t < n) ? g_indeg[t] : 0;
    sh[threadIdx.x] = v;
    __syncthreads();
    for (int o = 1; o < 256; o <<= 1) {
        int x = (threadIdx.x >= o) ? sh[threadIdx.x - o] : 0;
        __syncthreads();
        sh[threadIdx.x] += x;
        __syncthreads();
    }
    if (t < n) {
        int off = sh[threadIdx.x] - v + g_boff[blockIdx.x];
        g_off[t] = off;
        g_cursor[t] = off;
    }
}

// fill CSR: record = {src, att * norm[src] * scale[src]} packed as int2
__global__ void k_fill(const int* __restrict__ srcE, const int* __restrict__ dstE,
                       const int* __restrict__ srcA, const int* __restrict__ dstA,
                       const float* __restrict__ b_att, int eM, int eA) {
    int i = blockIdx.x * blockDim.x + threadIdx.x;
    int tot = eM + eA;
    if (i >= tot) return;
    int s, d; float a;
    if (i < eM) {
        s = srcE[i]; d = dstE[i]; a = g_att[i];
    } else {
        int j = i - eM;
        s = srcA[j]; d = dstA[j];
        a = 1.f / (1.f + __expf(-b_att[0]));
    }
    float c = a * g_ns[s];
    int pos = atomicAdd(&g_cursor[d], 1);
    g_edge[pos] = make_int2(s, __float_as_int(c));
}

// gather from int8 rows: warp per dst node; dequant scale folded into coef
__global__ void k_gather(int n) {
    int gtid = blockIdx.x * blockDim.x + threadIdx.x;
    int v = gtid >> 5;
    int lane = gtid & 31;
    if (v >= n) return;
    int off = g_off[v];
    int cnt = g_indeg[v];
    float4 acc = make_float4(0.f, 0.f, 0.f, 0.f);
    for (int base = 0; base < cnt; base += 32) {
        int m = cnt - base; if (m > 32) m = 32;
        int s = 0; float c = 0.f;
        if (lane < m) {
            int2 er = g_edge[off + base + lane];
            s = er.x;
            c = __int_as_float(er.y);
        }
#pragma unroll 8
        for (int i = 0; i < m; i++) {
            int   si = __shfl_sync(0xffffffffu, s, i);
            float ci = __shfl_sync(0xffffffffu, c, i);
            uint32_t w = g_h8[si * 32 + lane];
            float f0 = (float)((int)(w << 24) >> 24);
            float f1 = (float)((int)(w << 16) >> 24);
            float f2 = (float)((int)(w << 8) >> 24);
            float f3 = (float)((int)w >> 24);
            acc.x = fmaf(ci, f0, acc.x);
            acc.y = fmaf(ci, f1, acc.y);
            acc.z = fmaf(ci, f2, acc.z);
            acc.w = fmaf(ci, f3, acc.w);
        }
    }
    ((float4*)g_agg)[v * 32 + lane] = acc;
}

// ======================= mma.sync bf16x3 GEMM (unchanged) ===================
#define OFF_AH 0
#define OFF_AL 16384
#define OFF_BH 32768
#define OFF_BL 49152
#define OFF_WE 65536
#define OFF_BE 67584
#define OFF_BIAS 68096
#define SMEM_TOT 68608

__device__ __forceinline__ void ldmx4(uint32_t addr, uint32_t& r0, uint32_t& r1,
                                      uint32_t& r2, uint32_t& r3) {
    asm volatile("ldmatrix.sync.aligned.m8n8.x4.shared.b16 {%0,%1,%2,%3}, [%4];"
                 : "=r"(r0), "=r"(r1), "=r"(r2), "=r"(r3) : "r"(addr));
}
__device__ __forceinline__ void mma16816(float* c, const uint32_t* a,
                                         uint32_t b0, uint32_t b1) {
    asm volatile(
        "mma.sync.aligned.m16n8k16.row.col.f32.bf16.bf16.f32 "
        "{%0,%1,%2,%3}, {%4,%5,%6,%7}, {%8,%9}, {%0,%1,%2,%3};"
        : "+f"(c[0]), "+f"(c[1]), "+f"(c[2]), "+f"(c[3])
        : "r"(a[0]), "r"(a[1]), "r"(a[2]), "r"(a[3]), "r"(b0), "r"(b1));
}

__global__ void __launch_bounds__(256, 2)
k_gemm_mma(const float* __restrict__ feats,
           const float4* __restrict__ Wedge, const float* __restrict__ bedge,
           const float* __restrict__ bmsg, const float* __restrict__ bskip,
           float* __restrict__ C, int n) {
    extern __shared__ uint8_t sm[];
    uint32_t sb = smem_u32(sm);
    int tid = threadIdx.x;
    int lane = tid & 31;
    int wid = tid >> 5;
    int wm = wid & 3;
    int wn = wid >> 2;

    if (tid < DD) {
        ((float4*)(sm + OFF_WE))[tid] = Wedge[tid];
        ((float*)(sm + OFF_BE))[tid] = bedge[tid];
        ((float*)(sm + OFF_BIAS))[tid] = bmsg[tid] + bskip[tid];
    }

    int row = tid >> 1;
    int half = tid & 1;
    int grow = blockIdx.x * 128 + row;
    bool inb = grow < n;
    float4 efs = inb ? g_efsum[grow] : make_float4(0.f, 0.f, 0.f, 0.f);
    float ind = inb ? (float)g_indeg[grow] : 0.f;
    float nrm = inb ? g_norm[grow] : 0.f;

    const float4* agg4 = (const float4*)g_agg;
    const float4* fts4 = (const float4*)feats;
    const float4* sWe = (const float4*)(sm + OFF_WE);
    const float*  sBe = (const float*)(sm + OFF_BE);

    float acc[2][8][4];
#pragma unroll
    for (int mt = 0; mt < 2; mt++)
#pragma unroll
        for (int nf = 0; nf < 8; nf++)
#pragma unroll
            for (int e = 0; e < 4; e++) acc[mt][nf][e] = 0.f;

    int aRow = lane & 15;
    int aSeg = lane >> 4;
    int bq = lane >> 3;
    int bRowOff = ((bq >> 1) << 3) + (lane & 7);
    int bColSeg = bq & 1;

    for (int kc = 0; kc < 4; kc++) {
        __syncthreads();
        int phase = kc >> 1;
        int kc2 = kc & 1;
        {
            const float4* src = (const float4*)(g_Bt + kc * 32768);
            float4* dst = (float4*)(sm + OFF_BH);
#pragma unroll
            for (int i = 0; i < 8; i++) dst[tid + i * 256] = src[tid + i * 256];
        }
#pragma unroll
        for (int i = 0; i < 8; i++) {
            int c = half * 32 + i * 4;
            int gcol = kc2 * 64 + c;
            float v[4];
            if (phase == 0) {
                float4 a = inb ? agg4[grow * 32 + (gcol >> 2)] : make_float4(0, 0, 0, 0);
                float4 f = inb ? fts4[grow * 32 + (gcol >> 2)] : make_float4(0, 0, 0, 0);
                float av[4] = {a.x, a.y, a.z, a.w};
                float fv[4] = {f.x, f.y, f.z, f.w};
#pragma unroll
                for (int e = 0; e < 4; e++) {
                    float4 w = sWe[gcol + e];
                    float wef = w.x * efs.x + w.y * efs.y + w.z * efs.z + w.w * efs.w;
                    v[e] = (av[e] + wef + ind * (sBe[gcol + e] + fv[e] * nrm)) * nrm;
                }
            } else {
                float4 f = inb ? fts4[grow * 32 + (gcol >> 2)] : make_float4(0, 0, 0, 0);
                v[0] = f.x; v[1] = f.y; v[2] = f.z; v[3] = f.w;
            }
#pragma unroll
            for (int p = 0; p < 2; p++) {
                float v0 = v[2 * p], v1 = v[2 * p + 1];
                __nv_bfloat16 h0 = __float2bfloat16(v0), h1 = __float2bfloat16(v1);
                float l0 = v0 - __bfloat162float(h0), l1 = v1 - __bfloat162float(h1);
                __nv_bfloat16 q0 = __float2bfloat16(l0), q1 = __float2bfloat16(l1);
                uint32_t hw = (uint32_t)__bfloat16_as_ushort(h0) |
                              ((uint32_t)__bfloat16_as_ushort(h1) << 16);
                uint32_t lw = (uint32_t)__bfloat16_as_ushort(q0) |
                              ((uint32_t)__bfloat16_as_ushort(q1) << 16);
                uint32_t off = swz(row, c + 2 * p);
                *(uint32_t*)(sm + OFF_AH + off) = hw;
                *(uint32_t*)(sm + OFF_AL + off) = lw;
            }
        }
        __syncthreads();

#pragma unroll
        for (int ks = 0; ks < 4; ks++) {
            uint32_t ah[2][4], al[2][4];
#pragma unroll
            for (int mt = 0; mt < 2; mt++) {
                int r = wm * 32 + mt * 16 + aRow;
                int col = ks * 16 + aSeg * 8;
                uint32_t off = (uint32_t)(r * 128 + ((((col >> 3) ^ (r & 7)) << 4)));
                ldmx4(sb + OFF_AH + off, ah[mt][0], ah[mt][1], ah[mt][2], ah[mt][3]);
                ldmx4(sb + OFF_AL + off, al[mt][0], al[mt][1], al[mt][2], al[mt][3]);
            }
#pragma unroll
            for (int ntp = 0; ntp < 4; ntp++) {
                int r = wn * 64 + ntp * 16 + bRowOff;
                int col = ks * 16 + bColSeg * 8;
                uint32_t off = (uint32_t)(r * 128 + ((((col >> 3) ^ (r & 7)) << 4)));
                uint32_t bh[4], bl[4];
                ldmx4(sb + OFF_BH + off, bh[0], bh[1], bh[2], bh[3]);
                ldmx4(sb + OFF_BL + off, bl[0], bl[1], bl[2], bl[3]);
#pragma unroll
                for (int mt = 0; mt < 2; mt++) {
                    mma16816(acc[mt][ntp * 2], ah[mt], bh[0], bh[1]);
                    mma16816(acc[mt][ntp * 2], ah[mt], bl[0], bl[1]);
                    mma16816(acc[mt][ntp * 2], al[mt], bh[0], bh[1]);
                    mma16816(acc[mt][ntp * 2 + 1], ah[mt], bh[2], bh[3]);
                    mma16816(acc[mt][ntp * 2 + 1], ah[mt], bl[2], bl[3]);
                    mma16816(acc[mt][ntp * 2 + 1], al[mt], bh[2], bh[3]);
                }
            }
        }
    }

    const float* sBias = (const float*)(sm + OFF_BIAS);
#pragma unroll
    for (int mt = 0; mt < 2; mt++) {
        int r0 = blockIdx.x * 128 + wm * 32 + mt * 16 + (lane >> 2);
#pragma unroll
        for (int nf = 0; nf < 8; nf++) {
            int col = wn * 64 + nf * 8 + 2 * (lane & 3);
            float bx = sBias[col], by = sBias[col + 1];
            if (r0 < n) {
                float2 o = make_float2(acc[mt][nf][0] + bx, acc[mt][nf][1] + by);
                *(float2*)(C + r0 * DD + col) = o;
            }
            if (r0 + 8 < n) {
                float2 o = make_float2(acc[mt][nf][2] + bx, acc[mt][nf][3] + by);
                *(float2*)(C + (r0 + 8) * DD + col) = o;
            }
        }
    }
}

extern "C" void kernel_launch(void* const* d_in, const int* in_sizes, int n_in,
                              void* d_out, int out_size) {
    const float* feats      = (const float*)d_in[0];
    const float* edge_feats = (const float*)d_in[1];
    const int*   src_E      = (const int*)d_in[2];
    const int*   dst_E      = (const int*)d_in[3];
    const int*   src_acc    = (const int*)d_in[4];
    const int*   dst_acc    = (const int*)d_in[5];
    const float* W_skip     = (const float*)d_in[6];
    const float* b_skip     = (const float*)d_in[7];
    const float* W_msg      = (const float*)d_in[8];
    const float* b_msg      = (const float*)d_in[9];
    const float* W_edge     = (const float*)d_in[10];
    const float* b_edge     = (const float*)d_in[11];
    const float* W_att      = (const float*)d_in[12];
    const float* b_att      = (const float*)d_in[13];
    float* out = (float*)d_out;

    int n  = in_sizes[0] / DD;
    int eM = in_sizes[2];
    int eA = in_sizes[4];
    int nb = (n + 255) / 256;

    static int init_done = 0;
    static cudaStream_t s_side;
    static cudaEvent_t e_fork, e_join;
    if (!init_done) {
        cudaFuncSetAttribute(k_gemm_mma, cudaFuncAttributeMaxDynamicSharedMemorySize, SMEM_TOT);
        cudaStreamCreateWithFlags(&s_side, cudaStreamNonBlocking);
        cudaEventCreateWithFlags(&e_fork, cudaEventDisableTiming);
        cudaEventCreateWithFlags(&e_join, cudaEventDisableTiming);
        init_done = 1;
    }

    // fork: independent prep (int8 quantization + B prepack) on side stream
    cudaEventRecord(e_fork, 0);
    cudaStreamWaitEvent(s_side, e_fork, 0);
    k_h8<<<(n * 32 + 255) / 256, 256, 0, s_side>>>((const float4*)feats, n);
    k_prepB<<<64, 256, 0, s_side>>>(W_msg, W_skip);
    cudaEventRecord(e_join, s_side);

    // main chain
    k_init<<<128, 512>>>(n);
    k_count<<<2048, 512>>>(src_E, dst_E, (const float4*)edge_feats, dst_acc,
                           W_att, b_att, eM, eA);

    // join before scan1: scan1 reads g_scale (from k_h8)
    cudaStreamWaitEvent(0, e_join, 0);
    k_scan1<<<nb, 256>>>(n);
    k_scan2<<<1, NBMAX>>>(nb);
    k_scan3<<<nb, 256>>>(n);
    k_fill<<<(eM + eA + 255) / 256, 256>>>(src_E, dst_E, src_acc, dst_acc, b_att, eM, eA);

    k_gather<<<(n * 32 + 511) / 512, 512>>>(n);
    k_gemm_mma<<<(n + 127) / 128, 256, SMEM_TOT>>>(feats, (const float4*)W_edge, b_edge,
                                                   b_msg, b_skip, out, n);
}

// round 14
// speedup vs baseline: 1.0162x; 1.0162x over previous
#include <cuda_runtime.h>
#include <cuda_bf16.h>
#include <cuda_fp16.h>
#include <math.h>
#include <cstdint>

#define NN 100000
#define DD 128
#define EMAXM 1600000
#define EMAXT 1800000
#define NBMAX 512

// ---- static scratch (no allocation allowed; zero-initialized at load) ----
__device__ float  g_agg[NN * DD];
__device__ float  g_norm[NN];
__device__ int    g_deg[NN];      // zeroed by scan1 after use (replay-safe)
__device__ int    g_indeg[NN];    // zeroed by scan1 after copy to g_cnt
__device__ int    g_cnt[NN];      // stable indeg copy for scan23/gather/gemm
__device__ float4 g_efsum[NN];    // zeroed by scan1 after copy to g_efs2
__device__ float4 g_efs2[NN];     // stable efsum copy for gemm
__device__ int    g_off[NN];
__device__ int    g_cursor[NN];
__device__ int    g_bsum[NBMAX];
__device__ float  g_att[EMAXM];
__device__ int2   g_edge[EMAXT];          // CSR: {src, coef} grouped by dst
__device__ __align__(16) __half2 g_h16[NN * 64];   // fp16 copy of feats
__device__ __align__(16) uint8_t g_Bt[4 * 32768];  // prepacked B tiles

__device__ __forceinline__ void red_add_v4(float* p, float x, float y, float z, float w) {
    asm volatile("red.global.add.v4.f32 [%0], {%1,%2,%3,%4};"
                 :: "l"(p), "f"(x), "f"(y), "f"(z), "f"(w) : "memory");
}
__device__ __forceinline__ uint32_t smem_u32(const void* p) {
    uint32_t a;
    asm("{ .reg .u64 t; cvta.to.shared.u64 t, %1; cvt.u32.u64 %0, t; }" : "=r"(a) : "l"(p));
    return a;
}
// swizzled byte offset inside a 128-row x 64-col bf16 tile (128B rows)
__device__ __forceinline__ uint32_t swz(int row, int col) {
    return (uint32_t)(row * 128 + ((((col >> 3) ^ (row & 7)) << 4)) + ((col & 7) << 1));
}

// ======================= prep kernels (side stream) =========================
__global__ void k_h16(const float4* __restrict__ feats, int n) {
    int i = blockIdx.x * blockDim.x + threadIdx.x;
    int tot = n * 32;
    if (i >= tot) return;
    float4 f = feats[i];
    g_h16[i * 2]     = __floats2half2_rn(f.x, f.y);
    g_h16[i * 2 + 1] = __floats2half2_rn(f.z, f.w);
}

__global__ void k_prepB(const float* __restrict__ Wmsg, const float* __restrict__ Wskip) {
    int w = blockIdx.x * blockDim.x + threadIdx.x;
    if (w >= 16384) return;
    int phase = w >> 13;
    int j = (w >> 6) & 127;
    int k = (w & 63) * 2;
    const float* W = phase ? Wskip : Wmsg;
    float v0 = W[j * DD + k], v1 = W[j * DD + k + 1];
    __nv_bfloat16 h0 = __float2bfloat16(v0), h1 = __float2bfloat16(v1);
    float l0 = v0 - __bfloat162float(h0), l1 = v1 - __bfloat162float(h1);
    __nv_bfloat16 q0 = __float2bfloat16(l0), q1 = __float2bfloat16(l1);
    uint32_t hw = (uint32_t)__bfloat16_as_ushort(h0) | ((uint32_t)__bfloat16_as_ushort(h1) << 16);
    uint32_t lw = (uint32_t)__bfloat16_as_ushort(q0) | ((uint32_t)__bfloat16_as_ushort(q1) << 16);
    int tile = phase * 2 + (k >> 6);
    uint32_t off = swz(j, k & 63);
    *(uint32_t*)(g_Bt + tile * 32768 + off) = hw;
    *(uint32_t*)(g_Bt + tile * 32768 + 16384 + off) = lw;
}

// ======================= graph chain ========================================
__global__ void k_count(const int* __restrict__ srcE, const int* __restrict__ dstE,
                        const float4* __restrict__ ef, const int* __restrict__ dstA,
                        const float* __restrict__ W_att, const float* __restrict__ b_att,
                        int eM, int eA) {
    int stride = gridDim.x * blockDim.x;
    int i0 = blockIdx.x * blockDim.x + threadIdx.x;
    float w0 = W_att[0], w1 = W_att[1], w2 = W_att[2], w3 = W_att[3], bb = b_att[0];
    for (int e = i0; e < eM; e += stride) {
        atomicAdd(&g_deg[srcE[e]], 1);
        int d = dstE[e];
        atomicAdd(&g_indeg[d], 1);
        float4 f = ef[e];
        red_add_v4((float*)&g_efsum[d], f.x, f.y, f.z, f.w);
        float x = w0 * f.x + w1 * f.y + w2 * f.z + w3 * f.w + bb;
        g_att[e] = 1.f / (1.f + __expf(-x));
    }
    for (int e = i0; e < eA; e += stride)
        atomicAdd(&g_indeg[dstA[e]], 1);
}

// scan1: block sums of indeg; norm; copy indeg->g_cnt, efsum->g_efs2;
// zero deg/indeg/efsum for the next replay (replaces k_init).
__global__ void k_scan1(int n) {
    int t = blockIdx.x * 256 + threadIdx.x;
    int v = 0;
    if (t < n) {
        v = g_indeg[t];
        int dg = g_deg[t];
        g_norm[t] = (dg > 0) ? rsqrtf((float)dg) : 0.f;
        g_cnt[t] = v;
        g_efs2[t] = g_efsum[t];
        g_deg[t] = 0;
        g_indeg[t] = 0;
        g_efsum[t] = make_float4(0.f, 0.f, 0.f, 0.f);
    }
    __shared__ int sh[256];
    sh[threadIdx.x] = v;
    __syncthreads();
    for (int o = 128; o > 0; o >>= 1) {
        if (threadIdx.x < o) sh[threadIdx.x] += sh[threadIdx.x + o];
        __syncthreads();
    }
    if (threadIdx.x == 0) g_bsum[blockIdx.x] = sh[0];
}

// scan23: each block redundantly scans all block sums (<=512) to get its own
// offset, then does the per-element scan of its 256 cnt values.
__global__ void k_scan23(int nb, int n) {
    __shared__ int bs[NBMAX];
    __shared__ int sh[256];
    int t = threadIdx.x;
    int b = blockIdx.x;
    bs[t]       = (t < nb) ? g_bsum[t] : 0;
    bs[t + 256] = (t + 256 < nb) ? g_bsum[t + 256] : 0;
    int g = b * 256 + t;
    int v = (g < n) ? g_cnt[g] : 0;
    sh[t] = v;
    __syncthreads();
    // inclusive scan over 512 block sums (Hillis-Steele, 2 elems/thread)
    for (int o = 1; o < NBMAX; o <<= 1) {
        int x0 = (t >= o) ? bs[t - o] : 0;
        int x1 = (t + 256 >= o) ? bs[t + 256 - o] : 0;
        int s0 = bs[t], s1 = bs[t + 256];
        __syncthreads();
        bs[t] = s0 + x0;
        bs[t + 256] = s1 + x1;
        __syncthreads();
    }
    // inclusive scan of the 256 local values
    for (int o = 1; o < 256; o <<= 1) {
        int x = (t >= o) ? sh[t - o] : 0;
        __syncthreads();
        sh[t] += x;
        __syncthreads();
    }
    if (g < n) {
        int boff = (b == 0) ? 0 : bs[b - 1];
        int off = boff + sh[t] - v;
        g_off[g] = off;
        g_cursor[g] = off;
    }
}

// fill CSR: record = {src, att * norm[src]} packed as int2
__global__ void k_fill(const int* __restrict__ srcE, const int* __restrict__ dstE,
                       const int* __restrict__ srcA, const int* __restrict__ dstA,
                       const float* __restrict__ b_att, int eM, int eA) {
    int i = blockIdx.x * blockDim.x + threadIdx.x;
    int tot = eM + eA;
    if (i >= tot) return;
    int s, d; float a;
    if (i < eM) {
        s = srcE[i]; d = dstE[i]; a = g_att[i];
    } else {
        int j = i - eM;
        s = srcA[j]; d = dstA[j];
        a = 1.f / (1.f + __expf(-b_att[0]));
    }
    float c = a * g_norm[s];
    int pos = atomicAdd(&g_cursor[d], 1);
    g_edge[pos] = make_int2(s, __float_as_int(c));
}

// gather from fp16 feats copy: warp per dst node (R12 structure — best measured)
__global__ void k_gather(int n) {
    int gtid = blockIdx.x * blockDim.x + threadIdx.x;
    int v = gtid >> 5;
    int lane = gtid & 31;
    if (v >= n) return;
    int off = g_off[v];
    int cnt = g_cnt[v];
    const uint2* h16 = (const uint2*)g_h16;     // [NN*32] : 4 halves each
    float4 acc = make_float4(0.f, 0.f, 0.f, 0.f);
    for (int base = 0; base < cnt; base += 32) {
        int m = cnt - base; if (m > 32) m = 32;
        int s = 0; float c = 0.f;
        if (lane < m) {
            int2 er = g_edge[off + base + lane];
            s = er.x;
            c = __int_as_float(er.y);
        }
#pragma unroll 8
        for (int i = 0; i < m; i++) {
            int   si = __shfl_sync(0xffffffffu, s, i);
            float ci = __shfl_sync(0xffffffffu, c, i);
            uint2 hv = h16[si * 32 + lane];
            float2 fa = __half22float2(*(__half2*)&hv.x);
            float2 fb = __half22float2(*(__half2*)&hv.y);
            acc.x = fmaf(ci, fa.x, acc.x);
            acc.y = fmaf(ci, fa.y, acc.y);
            acc.z = fmaf(ci, fb.x, acc.z);
            acc.w = fmaf(ci, fb.y, acc.w);
        }
    }
    ((float4*)g_agg)[v * 32 + lane] = acc;
}

// ======================= mma.sync bf16x3 GEMM ===============================
#define OFF_AH 0
#define OFF_AL 16384
#define OFF_BH 32768
#define OFF_BL 49152
#define OFF_WE 65536
#define OFF_BE 67584
#define OFF_BIAS 68096
#define SMEM_TOT 68608

__device__ __forceinline__ void ldmx4(uint32_t addr, uint32_t& r0, uint32_t& r1,
                                      uint32_t& r2, uint32_t& r3) {
    asm volatile("ldmatrix.sync.aligned.m8n8.x4.shared.b16 {%0,%1,%2,%3}, [%4];"
                 : "=r"(r0), "=r"(r1), "=r"(r2), "=r"(r3) : "r"(addr));
}
__device__ __forceinline__ void mma16816(float* c, const uint32_t* a,
                                         uint32_t b0, uint32_t b1) {
    asm volatile(
        "mma.sync.aligned.m16n8k16.row.col.f32.bf16.bf16.f32 "
        "{%0,%1,%2,%3}, {%4,%5,%6,%7}, {%8,%9}, {%0,%1,%2,%3};"
        : "+f"(c[0]), "+f"(c[1]), "+f"(c[2]), "+f"(c[3])
        : "r"(a[0]), "r"(a[1]), "r"(a[2]), "r"(a[3]), "r"(b0), "r"(b1));
}

__global__ void __launch_bounds__(256, 2)
k_gemm_mma(const float* __restrict__ feats,
           const float4* __restrict__ Wedge, const float* __restrict__ bedge,
           const float* __restrict__ bmsg, const float* __restrict__ bskip,
           float* __restrict__ C, int n) {
    extern __shared__ uint8_t sm[];
    uint32_t sb = smem_u32(sm);
    int tid = threadIdx.x;
    int lane = tid & 31;
    int wid = tid >> 5;
    int wm = wid & 3;
    int wn = wid >> 2;

    if (tid < DD) {
        ((float4*)(sm + OFF_WE))[tid] = Wedge[tid];
        ((float*)(sm + OFF_BE))[tid] = bedge[tid];
        ((float*)(sm + OFF_BIAS))[tid] = bmsg[tid] + bskip[tid];
    }

    int row = tid >> 1;
    int half = tid & 1;
    int grow = blockIdx.x * 128 + row;
    bool inb = grow < n;
    float4 efs = inb ? g_efs2[grow] : make_float4(0.f, 0.f, 0.f, 0.f);
    float ind = inb ? (float)g_cnt[grow] : 0.f;
    float nrm = inb ? g_norm[grow] : 0.f;

    const float4* agg4 = (const float4*)g_agg;
    const float4* fts4 = (const float4*)feats;
    const float4* sWe = (const float4*)(sm + OFF_WE);
    const float*  sBe = (const float*)(sm + OFF_BE);

    float acc[2][8][4];
#pragma unroll
    for (int mt = 0; mt < 2; mt++)
#pragma unroll
        for (int nf = 0; nf < 8; nf++)
#pragma unroll
            for (int e = 0; e < 4; e++) acc[mt][nf][e] = 0.f;

    int aRow = lane & 15;
    int aSeg = lane >> 4;
    int bq = lane >> 3;
    int bRowOff = ((bq >> 1) << 3) + (lane & 7);
    int bColSeg = bq & 1;

    for (int kc = 0; kc < 4; kc++) {
        __syncthreads();
        int phase = kc >> 1;
        int kc2 = kc & 1;
        {
            const float4* src = (const float4*)(g_Bt + kc * 32768);
            float4* dst = (float4*)(sm + OFF_BH);
#pragma unroll
            for (int i = 0; i < 8; i++) dst[tid + i * 256] = src[tid + i * 256];
        }
#pragma unroll
        for (int i = 0; i < 8; i++) {
            int c = half * 32 + i * 4;
            int gcol = kc2 * 64 + c;
            float v[4];
            if (phase == 0) {
                float4 a = inb ? agg4[grow * 32 + (gcol >> 2)] : make_float4(0, 0, 0, 0);
                float4 f = inb ? fts4[grow * 32 + (gcol >> 2)] : make_float4(0, 0, 0, 0);
                float av[4] = {a.x, a.y, a.z, a.w};
                float fv[4] = {f.x, f.y, f.z, f.w};
#pragma unroll
                for (int e = 0; e < 4; e++) {
                    float4 w = sWe[gcol + e];
                    float wef = w.x * efs.x + w.y * efs.y + w.z * efs.z + w.w * efs.w;
                    v[e] = (av[e] + wef + ind * (sBe[gcol + e] + fv[e] * nrm)) * nrm;
                }
            } else {
                float4 f = inb ? fts4[grow * 32 + (gcol >> 2)] : make_float4(0, 0, 0, 0);
                v[0] = f.x; v[1] = f.y; v[2] = f.z; v[3] = f.w;
            }
#pragma unroll
            for (int p = 0; p < 2; p++) {
                float v0 = v[2 * p], v1 = v[2 * p + 1];
                __nv_bfloat16 h0 = __float2bfloat16(v0), h1 = __float2bfloat16(v1);
                float l0 = v0 - __bfloat162float(h0), l1 = v1 - __bfloat162float(h1);
                __nv_bfloat16 q0 = __float2bfloat16(l0), q1 = __float2bfloat16(l1);
                uint32_t hw = (uint32_t)__bfloat16_as_ushort(h0) |
                              ((uint32_t)__bfloat16_as_ushort(h1) << 16);
                uint32_t lw = (uint32_t)__bfloat16_as_ushort(q0) |
                              ((uint32_t)__bfloat16_as_ushort(q1) << 16);
                uint32_t off = swz(row, c + 2 * p);
                *(uint32_t*)(sm + OFF_AH + off) = hw;
                *(uint32_t*)(sm + OFF_AL + off) = lw;
            }
        }
        __syncthreads();

#pragma unroll
        for (int ks = 0; ks < 4; ks++) {
            uint32_t ah[2][4], al[2][4];
#pragma unroll
            for (int mt = 0; mt < 2; mt++) {
                int r = wm * 32 + mt * 16 + aRow;
                int col = ks * 16 + aSeg * 8;
                uint32_t off = (uint32_t)(r * 128 + ((((col >> 3) ^ (r & 7)) << 4)));
                ldmx4(sb + OFF_AH + off, ah[mt][0], ah[mt][1], ah[mt][2], ah[mt][3]);
                ldmx4(sb + OFF_AL + off, al[mt][0], al[mt][1], al[mt][2], al[mt][3]);
            }
#pragma unroll
            for (int ntp = 0; ntp < 4; ntp++) {
                int r = wn * 64 + ntp * 16 + bRowOff;
                int col = ks * 16 + bColSeg * 8;
                uint32_t off = (uint32_t)(r * 128 + ((((col >> 3) ^ (r & 7)) << 4)));
                uint32_t bh[4], bl[4];
                ldmx4(sb + OFF_BH + off, bh[0], bh[1], bh[2], bh[3]);
                ldmx4(sb + OFF_BL + off, bl[0], bl[1], bl[2], bl[3]);
#pragma unroll
                for (int mt = 0; mt < 2; mt++) {
                    mma16816(acc[mt][ntp * 2], ah[mt], bh[0], bh[1]);
                    mma16816(acc[mt][ntp * 2], ah[mt], bl[0], bl[1]);
                    mma16816(acc[mt][ntp * 2], al[mt], bh[0], bh[1]);
                    mma16816(acc[mt][ntp * 2 + 1], ah[mt], bh[2], bh[3]);
                    mma16816(acc[mt][ntp * 2 + 1], ah[mt], bl[2], bl[3]);
                    mma16816(acc[mt][ntp * 2 + 1], al[mt], bh[2], bh[3]);
                }
            }
        }
    }

    const float* sBias = (const float*)(sm + OFF_BIAS);
#pragma unroll
    for (int mt = 0; mt < 2; mt++) {
        int r0 = blockIdx.x * 128 + wm * 32 + mt * 16 + (lane >> 2);
#pragma unroll
        for (int nf = 0; nf < 8; nf++) {
            int col = wn * 64 + nf * 8 + 2 * (lane & 3);
            float bx = sBias[col], by = sBias[col + 1];
            if (r0 < n) {
                float2 o = make_float2(acc[mt][nf][0] + bx, acc[mt][nf][1] + by);
                *(float2*)(C + r0 * DD + col) = o;
            }
            if (r0 + 8 < n) {
                float2 o = make_float2(acc[mt][nf][2] + bx, acc[mt][nf][3] + by);
                *(float2*)(C + (r0 + 8) * DD + col) = o;
            }
        }
    }
}

extern "C" void kernel_launch(void* const* d_in, const int* in_sizes, int n_in,
                              void* d_out, int out_size) {
    const float* feats      = (const float*)d_in[0];
    const float* edge_feats = (const float*)d_in[1];
    const int*   src_E      = (const int*)d_in[2];
    const int*   dst_E      = (const int*)d_in[3];
    const int*   src_acc    = (const int*)d_in[4];
    const int*   dst_acc    = (const int*)d_in[5];
    const float* W_skip     = (const float*)d_in[6];
    const float* b_skip     = (const float*)d_in[7];
    const float* W_msg      = (const float*)d_in[8];
    const float* b_msg      = (const float*)d_in[9];
    const float* W_edge     = (const float*)d_in[10];
    const float* b_edge     = (const float*)d_in[11];
    const float* W_att      = (const float*)d_in[12];
    const float* b_att      = (const float*)d_in[13];
    float* out = (float*)d_out;

    int n  = in_sizes[0] / DD;
    int eM = in_sizes[2];
    int eA = in_sizes[4];
    int nb = (n + 255) / 256;

    static int init_done = 0;
    static cudaStream_t s_side;
    static cudaEvent_t e_fork, e_join;
    if (!init_done) {
        cudaFuncSetAttribute(k_gemm_mma, cudaFuncAttributeMaxDynamicSharedMemorySize, SMEM_TOT);
        cudaStreamCreateWithFlags(&s_side, cudaStreamNonBlocking);
        cudaEventCreateWithFlags(&e_fork, cudaEventDisableTiming);
        cudaEventCreateWithFlags(&e_join, cudaEventDisableTiming);
        init_done = 1;
    }

    // fork: independent prep (fp16 feats copy + B prepack) on side stream
    cudaEventRecord(e_fork, 0);
    cudaStreamWaitEvent(s_side, e_fork, 0);
    k_h16<<<(n * 32 + 255) / 256, 256, 0, s_side>>>((const float4*)feats, n);
    k_prepB<<<64, 256, 0, s_side>>>(W_msg, W_skip);
    cudaEventRecord(e_join, s_side);

    // main chain (no k_init: scan1 zeros counters for the next replay)
    k_count<<<2048, 512>>>(src_E, dst_E, (const float4*)edge_feats, dst_acc,
                           W_att, b_att, eM, eA);
    k_scan1<<<nb, 256>>>(n);
    k_scan23<<<nb, 256>>>(nb, n);
    k_fill<<<(eM + eA + 255) / 256, 256>>>(src_E, dst_E, src_acc, dst_acc, b_att, eM, eA);

    // join: gather needs g_h16, gemm needs g_Bt
    cudaStreamWaitEvent(0, e_join, 0);
    k_gather<<<(n * 32 + 511) / 512, 512>>>(n);
    k_gemm_mma<<<(n + 127) / 128, 256, SMEM_TOT>>>(feats, (const float4*)W_edge, b_edge,
                                                   b_msg, b_skip, out, n);
}

// round 16
// speedup vs baseline: 1.0666x; 1.0496x over previous
#include <cuda_runtime.h>
#include <cuda_bf16.h>
#include <cuda_fp16.h>
#include <math.h>
#include <cstdint>

#define NN 100000
#define DD 128
#define EMAXM 1600000
#define EMAXT 1800000
#define NBMAX 512
#define NTILES 800   // >= ceil(NN/128)

// ---- static scratch (no allocation allowed; zero-initialized at load) ----
__device__ float  g_norm[NN];
__device__ int    g_deg[NN];
__device__ int    g_indeg[NN];
__device__ int    g_cnt[NN];
__device__ float4 g_efsum[NN];
__device__ float4 g_efs2[NN];
__device__ int    g_off[NN];
__device__ int    g_cursor[NN];
__device__ int    g_bsum[NBMAX];
__device__ float  g_att[EMAXM];
__device__ int2   g_edge[EMAXT];
__device__ __align__(16) __half2 g_h16[NN * 64];        // fp16 feats for gather
__device__ __align__(16) uint8_t g_Bt[4 * 32768];       // B tiles (hi+lo)
__device__ __align__(16) uint8_t g_Ars[NTILES * 65536]; // rst A image (2 chunks x hi/lo)
__device__ __align__(16) uint8_t g_Afe[NTILES * 65536]; // feats A image

__device__ __forceinline__ void red_add_v4(float* p, float x, float y, float z, float w) {
    asm volatile("red.global.add.v4.f32 [%0], {%1,%2,%3,%4};"
                 :: "l"(p), "f"(x), "f"(y), "f"(z), "f"(w) : "memory");
}
__device__ __forceinline__ uint32_t smem_u32(const void* p) {
    uint32_t a;
    asm("{ .reg .u64 t; cvta.to.shared.u64 t, %1; cvt.u32.u64 %0, t; }" : "=r"(a) : "l"(p));
    return a;
}
__device__ __forceinline__ uint32_t swz(int row, int col) {
    return (uint32_t)(row * 128 + ((((col >> 3) ^ (row & 7)) << 4)) + ((col & 7) << 1));
}
__device__ __forceinline__ void bf16_split_pair(float v0, float v1, uint32_t& hw, uint32_t& lw) {
    __nv_bfloat16 h0 = __float2bfloat16(v0), h1 = __float2bfloat16(v1);
    float l0 = v0 - __bfloat162float(h0), l1 = v1 - __bfloat162float(h1);
    __nv_bfloat16 q0 = __float2bfloat16(l0), q1 = __float2bfloat16(l1);
    hw = (uint32_t)__bfloat16_as_ushort(h0) | ((uint32_t)__bfloat16_as_ushort(h1) << 16);
    lw = (uint32_t)__bfloat16_as_ushort(q0) | ((uint32_t)__bfloat16_as_ushort(q1) << 16);
}

// ======================= prep kernels (side stream) =========================
// fp16 copy for gather + feats bf16-split A-tile image for GEMM phase 1
__global__ void k_h16(const float4* __restrict__ feats, int n) {
    int i = blockIdx.x * blockDim.x + threadIdx.x;
    if (i >= n * 32) return;
    float4 f = feats[i];
    g_h16[i * 2]     = __floats2half2_rn(f.x, f.y);
    g_h16[i * 2 + 1] = __floats2half2_rn(f.z, f.w);
    int v = i >> 5, lane = i & 31;
    int tile = v >> 7, row = v & 127;
    int kc2 = lane >> 4;
    int lc = (lane * 4) & 63;
    uint32_t h0, l0, h1, l1;
    bf16_split_pair(f.x, f.y, h0, l0);
    bf16_split_pair(f.z, f.w, h1, l1);
    uint8_t* basep = g_Afe + (tile * 2 + kc2) * 32768 + swz(row, lc);
    *(uint2*)basep           = make_uint2(h0, h1);
    *(uint2*)(basep + 16384) = make_uint2(l0, l1);
}

__global__ void k_prepB(const float* __restrict__ Wmsg, const float* __restrict__ Wskip) {
    int w = blockIdx.x * blockDim.x + threadIdx.x;
    if (w >= 16384) return;
    int phase = w >> 13;
    int j = (w >> 6) & 127;
    int k = (w & 63) * 2;
    const float* W = phase ? Wskip : Wmsg;
    uint32_t hw, lw;
    bf16_split_pair(W[j * DD + k], W[j * DD + k + 1], hw, lw);
    int tile = phase * 2 + (k >> 6);
    uint32_t off = swz(j, k & 63);
    *(uint32_t*)(g_Bt + tile * 32768 + off) = hw;
    *(uint32_t*)(g_Bt + tile * 32768 + 16384 + off) = lw;
}

// ======================= graph chain ========================================
__global__ void k_count(const int* __restrict__ srcE, const int* __restrict__ dstE,
                        const float4* __restrict__ ef, const int* __restrict__ dstA,
                        const float* __restrict__ W_att, const float* __restrict__ b_att,
                        int eM, int eA) {
    int stride = gridDim.x * blockDim.x;
    int i0 = blockIdx.x * blockDim.x + threadIdx.x;
    float w0 = W_att[0], w1 = W_att[1], w2 = W_att[2], w3 = W_att[3], bb = b_att[0];
    for (int e = i0; e < eM; e += stride) {
        atomicAdd(&g_deg[srcE[e]], 1);
        int d = dstE[e];
        atomicAdd(&g_indeg[d], 1);
        float4 f = ef[e];
        red_add_v4((float*)&g_efsum[d], f.x, f.y, f.z, f.w);
        float x = w0 * f.x + w1 * f.y + w2 * f.z + w3 * f.w + bb;
        g_att[e] = 1.f / (1.f + __expf(-x));
    }
    for (int e = i0; e < eA; e += stride)
        atomicAdd(&g_indeg[dstA[e]], 1);
}

// scan1: block sums; norm; copy indeg->g_cnt, efsum->g_efs2; zero counters.
__global__ void k_scan1(int n) {
    int t = blockIdx.x * 256 + threadIdx.x;
    int v = 0;
    if (t < n) {
        v = g_indeg[t];
        int dg = g_deg[t];
        g_norm[t] = (dg > 0) ? rsqrtf((float)dg) : 0.f;
        g_cnt[t] = v;
        g_efs2[t] = g_efsum[t];
        g_deg[t] = 0;
        g_indeg[t] = 0;
        g_efsum[t] = make_float4(0.f, 0.f, 0.f, 0.f);
    }
    __shared__ int sh[256];
    sh[threadIdx.x] = v;
    __syncthreads();
    for (int o = 128; o > 0; o >>= 1) {
        if (threadIdx.x < o) sh[threadIdx.x] += sh[threadIdx.x + o];
        __syncthreads();
    }
    if (threadIdx.x == 0) g_bsum[blockIdx.x] = sh[0];
}

__global__ void k_scan23(int nb, int n) {
    __shared__ int bs[NBMAX];
    __shared__ int sh[256];
    int t = threadIdx.x;
    int b = blockIdx.x;
    bs[t]       = (t < nb) ? g_bsum[t] : 0;
    bs[t + 256] = (t + 256 < nb) ? g_bsum[t + 256] : 0;
    int g = b * 256 + t;
    int v = (g < n) ? g_cnt[g] : 0;
    sh[t] = v;
    __syncthreads();
    for (int o = 1; o < NBMAX; o <<= 1) {
        int x0 = (t >= o) ? bs[t - o] : 0;
        int x1 = (t + 256 >= o) ? bs[t + 256 - o] : 0;
        int s0 = bs[t], s1 = bs[t + 256];
        __syncthreads();
        bs[t] = s0 + x0;
        bs[t + 256] = s1 + x1;
        __syncthreads();
    }
    for (int o = 1; o < 256; o <<= 1) {
        int x = (t >= o) ? sh[t - o] : 0;
        __syncthreads();
        sh[t] += x;
        __syncthreads();
    }
    if (g < n) {
        int boff = (b == 0) ? 0 : bs[b - 1];
        int off = boff + sh[t] - v;
        g_off[g] = off;
        g_cursor[g] = off;
    }
}

__global__ void k_fill(const int* __restrict__ srcE, const int* __restrict__ dstE,
                       const int* __restrict__ srcA, const int* __restrict__ dstA,
                       const float* __restrict__ b_att, int eM, int eA) {
    int i = blockIdx.x * blockDim.x + threadIdx.x;
    int tot = eM + eA;
    if (i >= tot) return;
    int s, d; float a;
    if (i < eM) {
        s = srcE[i]; d = dstE[i]; a = g_att[i];
    } else {
        int j = i - eM;
        s = srcA[j]; d = dstA[j];
        a = 1.f / (1.f + __expf(-b_att[0]));
    }
    float c = a * g_norm[s];
    int pos = atomicAdd(&g_cursor[d], 1);
    g_edge[pos] = make_int2(s, __float_as_int(c));
}

// gather + fused rst epilogue + bf16 split -> A-tile image (warp per node)
__global__ void k_gather(const float4* __restrict__ feats,
                         const float4* __restrict__ Wedge,
                         const float* __restrict__ bedge, int n) {
    __shared__ float4 sWe[DD];
    __shared__ float  sBe[DD];
    int tid = threadIdx.x;
    if (tid < DD) { sWe[tid] = Wedge[tid]; sBe[tid] = bedge[tid]; }
    __syncthreads();
    int gtid = blockIdx.x * blockDim.x + tid;
    int v = gtid >> 5;
    int lane = gtid & 31;
    if (v >= n) return;
    int off = g_off[v];
    int cnt = g_cnt[v];
    const uint2* h16 = (const uint2*)g_h16;
    float4 acc = make_float4(0.f, 0.f, 0.f, 0.f);
    for (int base = 0; base < cnt; base += 32) {
        int m = cnt - base; if (m > 32) m = 32;
        int s = 0; float c = 0.f;
        if (lane < m) {
            int2 er = g_edge[off + base + lane];
            s = er.x;
            c = __int_as_float(er.y);
        }
#pragma unroll 8
        for (int i = 0; i < m; i++) {
            int   si = __shfl_sync(0xffffffffu, s, i);
            float ci = __shfl_sync(0xffffffffu, c, i);
            uint2 hv = h16[si * 32 + lane];
            float2 fa = __half22float2(*(__half2*)&hv.x);
            float2 fb = __half22float2(*(__half2*)&hv.y);
            acc.x = fmaf(ci, fa.x, acc.x);
            acc.y = fmaf(ci, fa.y, acc.y);
            acc.z = fmaf(ci, fb.x, acc.z);
            acc.w = fmaf(ci, fb.y, acc.w);
        }
    }
    // rst epilogue (exact math previously in the GEMM A-convert)
    float nrm = g_norm[v];
    float ind = (float)g_cnt[v];
    float4 efs = g_efs2[v];
    float4 f = feats[v * 32 + lane];
    int col = lane * 4;
    float av[4] = {acc.x, acc.y, acc.z, acc.w};
    float fv[4] = {f.x, f.y, f.z, f.w};
    float vout[4];
#pragma unroll
    for (int e = 0; e < 4; e++) {
        float4 w = sWe[col + e];
        float wef = w.x * efs.x + w.y * efs.y + w.z * efs.z + w.w * efs.w;
        vout[e] = (av[e] + wef + ind * (sBe[col + e] + fv[e] * nrm)) * nrm;
    }
    // bf16 split -> swizzled A image
    int tile = v >> 7, row = v & 127;
    int kc2 = lane >> 4;
    int lc = col & 63;
    uint32_t h0, l0, h1, l1;
    bf16_split_pair(vout[0], vout[1], h0, l0);
    bf16_split_pair(vout[2], vout[3], h1, l1);
    uint8_t* basep = g_Ars + (tile * 2 + kc2) * 32768 + swz(row, lc);
    *(uint2*)basep           = make_uint2(h0, h1);
    *(uint2*)(basep + 16384) = make_uint2(l0, l1);
}

// ======================= mma.sync bf16x3 GEMM (pure copy + MMA) =============
#define OFF_AH 0
#define OFF_AL 16384
#define OFF_BH 32768
#define OFF_BL 49152
#define OFF_BIAS 65536
#define SMEM_TOT 66048

__device__ __forceinline__ void ldmx4(uint32_t addr, uint32_t& r0, uint32_t& r1,
                                      uint32_t& r2, uint32_t& r3) {
    asm volatile("ldmatrix.sync.aligned.m8n8.x4.shared.b16 {%0,%1,%2,%3}, [%4];"
                 : "=r"(r0), "=r"(r1), "=r"(r2), "=r"(r3) : "r"(addr));
}
__device__ __forceinline__ void mma16816(float* c, const uint32_t* a,
                                         uint32_t b0, uint32_t b1) {
    asm volatile(
        "mma.sync.aligned.m16n8k16.row.col.f32.bf16.bf16.f32 "
        "{%0,%1,%2,%3}, {%4,%5,%6,%7}, {%8,%9}, {%0,%1,%2,%3};"
        : "+f"(c[0]), "+f"(c[1]), "+f"(c[2]), "+f"(c[3])
        : "r"(a[0]), "r"(a[1]), "r"(a[2]), "r"(a[3]), "r"(b0), "r"(b1));
}

__global__ void __launch_bounds__(256, 2)
k_gemm_mma(const float* __restrict__ bmsg, const float* __restrict__ bskip,
           float* __restrict__ C, int n) {
    extern __shared__ uint8_t sm[];
    uint32_t sb = smem_u32(sm);
    int tid = threadIdx.x;
    int lane = tid & 31;
    int wid = tid >> 5;
    int wm = wid & 3;
    int wn = wid >> 2;

    if (tid < DD) ((float*)(sm + OFF_BIAS))[tid] = bmsg[tid] + bskip[tid];

    float acc[2][8][4];
#pragma unroll
    for (int mt = 0; mt < 2; mt++)
#pragma unroll
        for (int nf = 0; nf < 8; nf++)
#pragma unroll
            for (int e = 0; e < 4; e++) acc[mt][nf][e] = 0.f;

    int aRow = lane & 15;
    int aSeg = lane >> 4;
    int bq = lane >> 3;
    int bRowOff = ((bq >> 1) << 3) + (lane & 7);
    int bColSeg = bq & 1;

    for (int kc = 0; kc < 4; kc++) {
        __syncthreads();
        const float4* srcB = (const float4*)(g_Bt + kc * 32768);
        const uint8_t* aimg = (kc >> 1) ? g_Afe : g_Ars;
        const float4* srcA = (const float4*)(aimg + ((size_t)blockIdx.x * 2 + (kc & 1)) * 32768);
        float4* dstA = (float4*)(sm + OFF_AH);
        float4* dstB = (float4*)(sm + OFF_BH);
#pragma unroll
        for (int i = 0; i < 8; i++) {
            dstA[tid + i * 256] = srcA[tid + i * 256];
            dstB[tid + i * 256] = srcB[tid + i * 256];
        }
        __syncthreads();

#pragma unroll
        for (int ks = 0; ks < 4; ks++) {
            uint32_t ah[2][4], al[2][4];
#pragma unroll
            for (int mt = 0; mt < 2; mt++) {
                int r = wm * 32 + mt * 16 + aRow;
                int col = ks * 16 + aSeg * 8;
                uint32_t off = (uint32_t)(r * 128 + ((((col >> 3) ^ (r & 7)) << 4)));
                ldmx4(sb + OFF_AH + off, ah[mt][0], ah[mt][1], ah[mt][2], ah[mt][3]);
                ldmx4(sb + OFF_AL + off, al[mt][0], al[mt][1], al[mt][2], al[mt][3]);
            }
#pragma unroll
            for (int ntp = 0; ntp < 4; ntp++) {
                int r = wn * 64 + ntp * 16 + bRowOff;
                int col = ks * 16 + bColSeg * 8;
                uint32_t off = (uint32_t)(r * 128 + ((((col >> 3) ^ (r & 7)) << 4)));
                uint32_t bh[4], bl[4];
                ldmx4(sb + OFF_BH + off, bh[0], bh[1], bh[2], bh[3]);
                ldmx4(sb + OFF_BL + off, bl[0], bl[1], bl[2], bl[3]);
#pragma unroll
                for (int mt = 0; mt < 2; mt++) {
                    mma16816(acc[mt][ntp * 2], ah[mt], bh[0], bh[1]);
                    mma16816(acc[mt][ntp * 2], ah[mt], bl[0], bl[1]);
                    mma16816(acc[mt][ntp * 2], al[mt], bh[0], bh[1]);
                    mma16816(acc[mt][ntp * 2 + 1], ah[mt], bh[2], bh[3]);
                    mma16816(acc[mt][ntp * 2 + 1], ah[mt], bl[2], bl[3]);
                    mma16816(acc[mt][ntp * 2 + 1], al[mt], bh[2], bh[3]);
                }
            }
        }
    }

    const float* sBias = (const float*)(sm + OFF_BIAS);
#pragma unroll
    for (int mt = 0; mt < 2; mt++) {
        int r0 = blockIdx.x * 128 + wm * 32 + mt * 16 + (lane >> 2);
#pragma unroll
        for (int nf = 0; nf < 8; nf++) {
            int col = wn * 64 + nf * 8 + 2 * (lane & 3);
            float bx = sBias[col], by = sBias[col + 1];
            if (r0 < n) {
                float2 o = make_float2(acc[mt][nf][0] + bx, acc[mt][nf][1] + by);
                *(float2*)(C + r0 * DD + col) = o;
            }
            if (r0 + 8 < n) {
                float2 o = make_float2(acc[mt][nf][2] + bx, acc[mt][nf][3] + by);
                *(float2*)(C + (r0 + 8) * DD + col) = o;
            }
        }
    }
}

extern "C" void kernel_launch(void* const* d_in, const int* in_sizes, int n_in,
                              void* d_out, int out_size) {
    const float* feats      = (const float*)d_in[0];
    const float* edge_feats = (const float*)d_in[1];
    const int*   src_E      = (const int*)d_in[2];
    const int*   dst_E      = (const int*)d_in[3];
    const int*   src_acc    = (const int*)d_in[4];
    const int*   dst_acc    = (const int*)d_in[5];
    const float* W_skip     = (const float*)d_in[6];
    const float* b_skip     = (const float*)d_in[7];
    const float* W_msg      = (const float*)d_in[8];
    const float* b_msg      = (const float*)d_in[9];
    const float* W_edge     = (const float*)d_in[10];
    const float* b_edge     = (const float*)d_in[11];
    const float* W_att      = (const float*)d_in[12];
    const float* b_att      = (const float*)d_in[13];
    float* out = (float*)d_out;

    int n  = in_sizes[0] / DD;
    int eM = in_sizes[2];
    int eA = in_sizes[4];
    int nb = (n + 255) / 256;

    static int init_done = 0;
    static cudaStream_t s_side;
    static cudaEvent_t e_fork, e_join;
    if (!init_done) {
        cudaFuncSetAttribute(k_gemm_mma, cudaFuncAttributeMaxDynamicSharedMemorySize, SMEM_TOT);
        cudaStreamCreateWithFlags(&s_side, cudaStreamNonBlocking);
        cudaEventCreateWithFlags(&e_fork, cudaEventDisableTiming);
        cudaEventCreateWithFlags(&e_join, cudaEventDisableTiming);
        init_done = 1;
    }

    // fork: fp16 copy + feats A-image + B prepack on side stream
    cudaEventRecord(e_fork, 0);
    cudaStreamWaitEvent(s_side, e_fork, 0);
    k_h16<<<(n * 32 + 255) / 256, 256, 0, s_side>>>((const float4*)feats, n);
    k_prepB<<<64, 256, 0, s_side>>>(W_msg, W_skip);
    cudaEventRecord(e_join, s_side);

    // main chain
    k_count<<<2048, 512>>>(src_E, dst_E, (const float4*)edge_feats, dst_acc,
                           W_att, b_att, eM, eA);
    k_scan1<<<nb, 256>>>(n);
    k_scan23<<<nb, 256>>>(nb, n);
    k_fill<<<(eM + eA + 255) / 256, 256>>>(src_E, dst_E, src_acc, dst_acc, b_att, eM, eA);

    // join: gather needs g_h16; gemm needs g_Bt/g_Afe
    cudaStreamWaitEvent(0, e_join, 0);
    k_gather<<<(n * 32 + 511) / 512, 512>>>((const float4*)feats, (const float4*)W_edge,
                                            b_edge, n);
    k_gemm_mma<<<(n + 127) / 128, 256, SMEM_TOT>>>(b_msg, b_skip, out, n);
}